// round 11
// baseline (speedup 1.0000x reference)
#include <cuda_runtime.h>
#include <cuda_fp16.h>
#include <cstdint>

// ---------------------------------------------------------------------------
// ResidualGNNLayer (sm_103, fp16 mma.sync, 64x64 warp tiles, dbl-buf frags):
//   k_prep: detect + zero + W1/W2 fp16 transpose + x->fp16
//   k_edge: bucket edges; k_feat: 2 nodes/warp fp16 gather-mean
//   k_gemm1: h = relu(feat@W1 + b1 + rank2(deg,md))
//   k_gemm2: out = LN(x + h@W2 + b2)
//   GEMMs: 128 thr / 4 warps (2x2) of 64x64, BK=32, 3-stage, 2 CTAs/SM.
// ---------------------------------------------------------------------------

#define DD 128
#define HH 512
#define KP 256
#define CAP 128
#define NN_MAX 50048    // 391 * 128

static __device__ int   g_is64;
static __device__ int   g_cnt[NN_MAX];
static __device__ float g_dist[NN_MAX];
static __device__ int   g_slots[NN_MAX * CAP];

static __device__ __half g_xh[(size_t)NN_MAX * DD];
static __device__ __half g_feat[(size_t)NN_MAX * KP];
static __device__ __half g_h[(size_t)NN_MAX * HH];
static __device__ __half g_w1t[HH * KP];              // [n=512][k=256]
static __device__ __half g_w2t[DD * HH];              // [n=128][k=512]

// ---------------- PTX helpers ----------------------------------------------
__device__ __forceinline__ uint32_t smem_u32(const void* p) {
    uint32_t a;
    asm("{ .reg .u64 t; cvta.to.shared.u64 t, %1; cvt.u32.u64 %0, t; }"
        : "=r"(a) : "l"(p));
    return a;
}
__device__ __forceinline__ void cp16(uint32_t d, const void* s) {
    asm volatile("cp.async.ca.shared.global [%0], [%1], 16;" :: "r"(d), "l"(s));
}
#define CP_COMMIT() asm volatile("cp.async.commit_group;" ::: "memory")
#define CP_WAIT(n)  asm volatile("cp.async.wait_group %0;" :: "n"(n) : "memory")

__device__ __forceinline__ void ldm_x4(uint32_t addr, uint32_t r[4]) {
    asm volatile("ldmatrix.sync.aligned.m8n8.x4.shared.b16 {%0,%1,%2,%3}, [%4];"
                 : "=r"(r[0]), "=r"(r[1]), "=r"(r[2]), "=r"(r[3]) : "r"(addr));
}
__device__ __forceinline__ void mma16816(float d[4], const uint32_t a[4],
                                         const uint32_t b0, const uint32_t b1) {
    asm volatile(
        "mma.sync.aligned.m16n8k16.row.col.f32.f16.f16.f32 "
        "{%0,%1,%2,%3},{%4,%5,%6,%7},{%8,%9},{%0,%1,%2,%3};"
        : "+f"(d[0]), "+f"(d[1]), "+f"(d[2]), "+f"(d[3])
        : "r"(a[0]), "r"(a[1]), "r"(a[2]), "r"(a[3]), "r"(b0), "r"(b1));
}
__device__ __forceinline__ uint32_t swz(int r, int c) {
    return (uint32_t)(r * 64 + (((((c >> 4) ^ (r >> 1)) & 3) << 4) | (c & 15)));
}

// ---------------- prep ------------------------------------------------------
__global__ void k_prep(const float* __restrict__ W1, const float* __restrict__ W2,
                       const float* __restrict__ x,
                       const void* __restrict__ eraw, int E, int Nn) {
    int b = blockIdx.x, t = threadIdx.x;
    if (b == 0) {
        if (t == 0) {
            const long long* p64 = (const long long*)eraw;
            int ok64 = 1;
            int step = E / 32; if (step < 1) step = 1;
            for (int i = 0; i < 32; i++) {
                long long idx = (long long)i * step;
                if (idx >= E) break;
                long long v = p64[idx];
                if (v < 0 || v >= Nn) { ok64 = 0; break; }
            }
            g_is64 = ok64;
        }
        return;
    }
    int ZB = (Nn + 255) / 256;
    if (b - 1 < ZB) {
        int i = (b - 1) * 256 + t;
        if (i < Nn) { g_cnt[i] = 0; g_dist[i] = 0.f; }
        return;
    }
    int b2 = b - 1 - ZB;
    if (b2 < (HH * KP) / 256) {
        int idx = b2 * 256 + t;
        int n = idx >> 8, k = idx & 255;
        g_w1t[idx] = __float2half_rn(W1[k * HH + n]);
        return;
    }
    int b3 = b2 - (HH * KP) / 256;
    if (b3 < (DD * HH) / 256) {
        int idx = b3 * 256 + t;
        int n = idx >> 9, k = idx & 511;
        g_w2t[idx] = __float2half_rn(W2[k * DD + n]);
        return;
    }
    int b4 = b3 - (DD * HH) / 256;
    int idx = b4 * 256 + t;
    if (idx < Nn * DD) g_xh[idx] = __float2half_rn(x[idx]);
}

__global__ void k_edge(const void* __restrict__ eraw,
                       const float* __restrict__ ed, int E, int Nn) {
    int e = blockIdx.x * blockDim.x + threadIdx.x;
    if (e >= E) return;
    int src, dst;
    if (g_is64) {
        const long long* p = (const long long*)eraw;
        src = (int)p[e]; dst = (int)p[E + e];
    } else {
        const int* p = (const int*)eraw;
        src = p[e]; dst = p[E + e];
    }
    src = min(max(src, 0), Nn - 1);
    dst = min(max(dst, 0), Nn - 1);
    int p = atomicAdd(&g_cnt[src], 1);
    if (p < CAP) g_slots[src * CAP + p] = dst;
    atomicAdd(&g_dist[src], ed[e]);
}

// 2 nodes per warp: 16 lanes x uint4 (16B) per row; doubles gather MLP
__global__ void k_feat(const float* __restrict__ degrees, int Nn) {
    int warp = (blockIdx.x * blockDim.x + threadIdx.x) >> 5;
    int lane = threadIdx.x & 31;
    int sub = lane >> 4, sl = lane & 15;
    int gw = warp * 2 + sub;
    if (gw >= Nn) return;
    int cnt = g_cnt[gw]; if (cnt > CAP) cnt = CAP;
    const int* slots = g_slots + gw * CAP;
    float acc[8];
#pragma unroll
    for (int i = 0; i < 8; i++) acc[i] = 0.f;
    int dnext = (cnt > 0) ? slots[0] : 0;
    for (int j = 0; j < cnt; j++) {
        int dcur = dnext;
        if (j + 1 < cnt) dnext = slots[j + 1];
        uint4 u = *(const uint4*)(g_xh + (size_t)dcur * DD + sl * 8);
        float2 f0 = __half22float2(*(__half2*)&u.x);
        float2 f1 = __half22float2(*(__half2*)&u.y);
        float2 f2 = __half22float2(*(__half2*)&u.z);
        float2 f3 = __half22float2(*(__half2*)&u.w);
        acc[0] += f0.x; acc[1] += f0.y; acc[2] += f1.x; acc[3] += f1.y;
        acc[4] += f2.x; acc[5] += f2.y; acc[6] += f3.x; acc[7] += f3.y;
    }
    float inv = 1.f / fmaxf(degrees[gw], 1.f);
    __half* f = g_feat + (size_t)gw * KP;
    *(uint4*)(f + sl * 8) = *(const uint4*)(g_xh + (size_t)gw * DD + sl * 8);
    uint4 o;
    *(__half2*)&o.x = __floats2half2_rn(acc[0] * inv, acc[1] * inv);
    *(__half2*)&o.y = __floats2half2_rn(acc[2] * inv, acc[3] * inv);
    *(__half2*)&o.z = __floats2half2_rn(acc[4] * inv, acc[5] * inv);
    *(__half2*)&o.w = __floats2half2_rn(acc[6] * inv, acc[7] * inv);
    *(uint4*)(f + DD + sl * 8) = o;
}

// ---------------------------------------------------------------------------
// GEMM common: CTA 128x128, 4 warps (2x2) of 64x64, BK=32, 3 stages.
// Stage 16KB: A @0 (128r x 64B swizzled), B @8192.
// Fragment address algebra: addr(mf+1)=addr(mf)+1024; addr(ks1)=addr(ks0)^32.
// ---------------------------------------------------------------------------
#define STG(s) ((s) * 16384)

struct Frag64 {
    uint32_t Ah[4][4];
    uint32_t Bh[8][2];
};
__device__ __forceinline__ void load_f(uint32_t sb, uint32_t aoff, uint32_t boff,
                                       Frag64& f) {
#pragma unroll
    for (int mf = 0; mf < 4; mf++)
        ldm_x4(sb + aoff + mf * 1024, f.Ah[mf]);
#pragma unroll
    for (int p = 0; p < 4; p++) {
        uint32_t r[4];
        ldm_x4(sb + boff + p * 1024, r);
        f.Bh[p * 2 + 0][0] = r[0]; f.Bh[p * 2 + 0][1] = r[2];
        f.Bh[p * 2 + 1][0] = r[1]; f.Bh[p * 2 + 1][1] = r[3];
    }
}
__device__ __forceinline__ void mma_all64(float acc[4][8][4], const Frag64& f) {
#pragma unroll
    for (int mf = 0; mf < 4; mf++)
#pragma unroll
        for (int nf = 0; nf < 8; nf++)
            mma16816(acc[mf][nf], f.Ah[mf], f.Bh[nf][0], f.Bh[nf][1]);
}

// ---------------------------------------------------------------------------
// GEMM1: h = relu(feat @ W1 + b1 + deg*W1[256] + md*W1[257]); K=256, 8 steps
// ---------------------------------------------------------------------------
#define G1_SMEM 50176
__global__ __launch_bounds__(128, 2) void k_gemm1(
    const float* __restrict__ W1, const float* __restrict__ b1,
    const float* __restrict__ degrees, int Nn) {
    extern __shared__ __align__(128) char sm[];
    uint32_t base = smem_u32(sm);
    int t = threadIdx.x, lane = t & 31, wid = t >> 5;
    int wm = wid >> 1, wn = wid & 1;
    int row0 = blockIdx.x * 128, col0 = blockIdx.y * 128;

    float* degv = (float*)(sm + 49152);
    float* mdv  = (float*)(sm + 49664);
    {
        int gr = row0 + t;
        float dr = (gr < Nn) ? degrees[gr] : 0.f;
        float ds = (gr < Nn) ? g_dist[gr] : 0.f;
        degv[t] = dr;
        mdv[t]  = ds / fmaxf(dr, 1.f);
    }

    float acc[4][8][4];
#pragma unroll
    for (int a = 0; a < 4; a++)
#pragma unroll
        for (int b = 0; b < 8; b++)
#pragma unroll
            for (int c = 0; c < 4; c++) acc[a][b][c] = 0.f;

    uint32_t aoff = swz(wm * 64 + (lane & 15), (lane >> 4) * 16);
    uint32_t boff = 8192 + swz(wn * 64 + (lane & 15), (lane >> 4) * 16);

    int lr = t >> 2, seg = (t & 3) * 16;
    const char* pA = (const char*)(g_feat + (size_t)(row0 + lr) * KP) + seg;
    const char* pB = (const char*)(g_w1t + (size_t)(col0 + lr) * KP) + seg;
    uint32_t dA = base + swz(lr, seg);
    const int RB = KP * 2 * 32;   // 32 source rows = 16384 B

#pragma unroll 1
    for (int s = 0; s < 2; s++) {
#pragma unroll
        for (int i = 0; i < 4; i++) {
            cp16(dA + STG(s) + 2048 * i, pA + i * RB + s * 64);
            cp16(dA + STG(s) + 8192 + 2048 * i, pB + i * RB + s * 64);
        }
        CP_COMMIT();
    }
#pragma unroll 1
    for (int s = 0; s < 8; s++) {
        if (s < 7) { CP_WAIT(1); } else { CP_WAIT(0); }
        __syncthreads();
        if (s + 2 < 8) {
            int sp = (s + 2) % 3;
#pragma unroll
            for (int i = 0; i < 4; i++) {
                cp16(dA + STG(sp) + 2048 * i, pA + i * RB + (s + 2) * 64);
                cp16(dA + STG(sp) + 8192 + 2048 * i, pB + i * RB + (s + 2) * 64);
            }
            CP_COMMIT();
        }
        uint32_t sb = base + STG(s % 3);
        Frag64 f0, f1;
        load_f(sb, aoff, boff, f0);
        load_f(sb, aoff ^ 32u, boff ^ 32u, f1);
        mma_all64(acc, f0);
        mma_all64(acc, f1);
    }

    // epilogue: bias + rank2 + relu -> g_h fp16
#pragma unroll
    for (int nf = 0; nf < 8; nf++) {
        int cg = col0 + wn * 64 + nf * 8 + (lane & 3) * 2;
        float b10 = __ldg(b1 + cg), b11 = __ldg(b1 + cg + 1);
        float wd0 = __ldg(W1 + 256 * HH + cg), wd1 = __ldg(W1 + 256 * HH + cg + 1);
        float wq0 = __ldg(W1 + 257 * HH + cg), wq1 = __ldg(W1 + 257 * HH + cg + 1);
#pragma unroll
        for (int mf = 0; mf < 4; mf++) {
            int rl = wm * 64 + mf * 16 + (lane >> 2);
            float d0 = degv[rl], m0 = mdv[rl];
            float d1 = degv[rl + 8], m1 = mdv[rl + 8];
            float v00 = fmaxf(acc[mf][nf][0] + b10 + d0 * wd0 + m0 * wq0, 0.f);
            float v01 = fmaxf(acc[mf][nf][1] + b11 + d0 * wd1 + m0 * wq1, 0.f);
            float v10 = fmaxf(acc[mf][nf][2] + b10 + d1 * wd0 + m1 * wq0, 0.f);
            float v11 = fmaxf(acc[mf][nf][3] + b11 + d1 * wd1 + m1 * wq1, 0.f);
            *(__half2*)(g_h + (size_t)(row0 + rl) * HH + cg) =
                __floats2half2_rn(v00, v01);
            *(__half2*)(g_h + (size_t)(row0 + rl + 8) * HH + cg) =
                __floats2half2_rn(v10, v11);
        }
    }
}

// ---------------------------------------------------------------------------
// GEMM2 + residual + LN: out = LN(x + h@W2 + b2); K=512, 16 steps
// ---------------------------------------------------------------------------
#define G2_SMEM 52224
__global__ __launch_bounds__(128, 2) void k_gemm2(
    const float* __restrict__ x, const float* __restrict__ b2,
    const float* __restrict__ gamma, const float* __restrict__ beta,
    float* __restrict__ out, int Nn) {
    extern __shared__ __align__(128) char sm[];
    uint32_t base = smem_u32(sm);
    int t = threadIdx.x, lane = t & 31, wid = t >> 5;
    int wm = wid >> 1, wn = wid & 1;
    int row0 = blockIdx.x * 128;
    float* part0 = (float*)(sm + 49152);
    float* part1 = (float*)(sm + 50176);
    float* mus   = (float*)(sm + 51200);
    float* rss   = (float*)(sm + 51712);

    float acc[4][8][4];
#pragma unroll
    for (int a = 0; a < 4; a++)
#pragma unroll
        for (int b = 0; b < 8; b++)
#pragma unroll
            for (int c = 0; c < 4; c++) acc[a][b][c] = 0.f;

    uint32_t aoff = swz(wm * 64 + (lane & 15), (lane >> 4) * 16);
    uint32_t boff = 8192 + swz(wn * 64 + (lane & 15), (lane >> 4) * 16);

    int lr = t >> 2, seg = (t & 3) * 16;
    const char* pA = (const char*)(g_h + (size_t)(row0 + lr) * HH) + seg;
    const char* pB = (const char*)(g_w2t + (size_t)lr * HH) + seg;
    uint32_t dA = base + swz(lr, seg);
    const int RB = HH * 2 * 32;   // 32 source rows = 32768 B

#pragma unroll 1
    for (int s = 0; s < 2; s++) {
#pragma unroll
        for (int i = 0; i < 4; i++) {
            cp16(dA + STG(s) + 2048 * i, pA + i * RB + s * 64);
            cp16(dA + STG(s) + 8192 + 2048 * i, pB + i * RB + s * 64);
        }
        CP_COMMIT();
    }
#pragma unroll 1
    for (int s = 0; s < 16; s++) {
        if (s < 15) { CP_WAIT(1); } else { CP_WAIT(0); }
        __syncthreads();
        if (s + 2 < 16) {
            int sp = (s + 2) % 3;
#pragma unroll
            for (int i = 0; i < 4; i++) {
                cp16(dA + STG(sp) + 2048 * i, pA + i * RB + (s + 2) * 64);
                cp16(dA + STG(sp) + 8192 + 2048 * i, pB + i * RB + (s + 2) * 64);
            }
            CP_COMMIT();
        }
        uint32_t sb = base + STG(s % 3);
        Frag64 f0, f1;
        load_f(sb, aoff, boff, f0);
        load_f(sb, aoff ^ 32u, boff ^ 32u, f1);
        mma_all64(acc, f0);
        mma_all64(acc, f1);
    }

    // epilogue: y = acc + b2 + x in regs; row stats via quad-shfl + smem
#pragma unroll
    for (int nf = 0; nf < 8; nf++) {
        int cc = wn * 64 + nf * 8 + (lane & 3) * 2;
        float b20 = __ldg(b2 + cc), b21 = __ldg(b2 + cc + 1);
#pragma unroll
        for (int mf = 0; mf < 4; mf++) {
            int g0 = row0 + wm * 64 + mf * 16 + (lane >> 2);
            float2 xv0 = make_float2(0.f, 0.f), xv1 = xv0;
            if (g0 < Nn)     xv0 = *(const float2*)(x + (size_t)g0 * DD + cc);
            if (g0 + 8 < Nn) xv1 = *(const float2*)(x + (size_t)(g0 + 8) * DD + cc);
            acc[mf][nf][0] += b20 + xv0.x;
            acc[mf][nf][1] += b21 + xv0.y;
            acc[mf][nf][2] += b20 + xv1.x;
            acc[mf][nf][3] += b21 + xv1.y;
        }
    }
#pragma unroll
    for (int mf = 0; mf < 4; mf++) {
#pragma unroll
        for (int h = 0; h < 2; h++) {
            float s0 = 0.f, s1 = 0.f;
#pragma unroll
            for (int nf = 0; nf < 8; nf++) {
                float a0 = acc[mf][nf][2 * h], a1 = acc[mf][nf][2 * h + 1];
                s0 += a0 + a1;
                s1 += a0 * a0 + a1 * a1;
            }
            s0 += __shfl_xor_sync(0xffffffffu, s0, 1);
            s1 += __shfl_xor_sync(0xffffffffu, s1, 1);
            s0 += __shfl_xor_sync(0xffffffffu, s0, 2);
            s1 += __shfl_xor_sync(0xffffffffu, s1, 2);
            if ((lane & 3) == 0) {
                int rl = wm * 64 + mf * 16 + (lane >> 2) + h * 8;
                part0[wn * 128 + rl] = s0;
                part1[wn * 128 + rl] = s1;
            }
        }
    }
    __syncthreads();
    {
        float s0 = part0[t] + part0[128 + t];
        float s1 = part1[t] + part1[128 + t];
        float mu = s0 * (1.f / 128.f);
        float var = s1 * (1.f / 128.f) - mu * mu;
        mus[t] = mu;
        rss[t] = rsqrtf(var + 1e-5f);
    }
    __syncthreads();
#pragma unroll
    for (int nf = 0; nf < 8; nf++) {
        int cc = wn * 64 + nf * 8 + (lane & 3) * 2;
        float gg0 = __ldg(gamma + cc), gg1 = __ldg(gamma + cc + 1);
        float be0 = __ldg(beta + cc), be1 = __ldg(beta + cc + 1);
#pragma unroll
        for (int mf = 0; mf < 4; mf++) {
            int rl = wm * 64 + mf * 16 + (lane >> 2);
            int g0 = row0 + rl;
            if (g0 < Nn) {
                float mu = mus[rl], rs = rss[rl];
                float2 o;
                o.x = (acc[mf][nf][0] - mu) * rs * gg0 + be0;
                o.y = (acc[mf][nf][1] - mu) * rs * gg1 + be1;
                *(float2*)(out + (size_t)g0 * DD + cc) = o;
            }
            if (g0 + 8 < Nn) {
                float mu = mus[rl + 8], rs = rss[rl + 8];
                float2 o;
                o.x = (acc[mf][nf][2] - mu) * rs * gg0 + be0;
                o.y = (acc[mf][nf][3] - mu) * rs * gg1 + be1;
                *(float2*)(out + (size_t)(g0 + 8) * DD + cc) = o;
            }
        }
    }
}

// ---------------------------------------------------------------------------
extern "C" void kernel_launch(void* const* d_in, const int* in_sizes, int n_in,
                              void* d_out, int out_size) {
    const float* x       = (const float*)d_in[0];
    const float* W1      = (const float*)d_in[1];
    const float* b1      = (const float*)d_in[2];
    const float* W2      = (const float*)d_in[3];
    const float* b2      = (const float*)d_in[4];
    const float* gamma   = (const float*)d_in[5];
    const float* beta    = (const float*)d_in[6];
    const void*  ei      = d_in[7];
    const float* ed      = (const float*)d_in[8];
    const float* degrees = (const float*)d_in[9];

    int Nn = in_sizes[0] / DD;
    int E  = in_sizes[8];

    cudaFuncSetAttribute(k_gemm1, cudaFuncAttributeMaxDynamicSharedMemorySize, G1_SMEM);
    cudaFuncSetAttribute(k_gemm2, cudaFuncAttributeMaxDynamicSharedMemorySize, G2_SMEM);

    int ZB = (Nn + 255) / 256;
    int XB = (Nn * DD + 255) / 256;
    int prep_blocks = 1 + ZB + (HH * KP) / 256 + (DD * HH) / 256 + XB;
    k_prep<<<prep_blocks, 256>>>(W1, W2, x, ei, E, Nn);
    k_edge<<<(E + 255) / 256, 256>>>(ei, ed, E, Nn);
    k_feat<<<(Nn + 15) / 16, 256>>>(degrees, Nn);

    int mt = (Nn + 127) / 128;  // 391
    k_gemm1<<<dim3(mt, 4), 128, G1_SMEM>>>(W1, b1, degrees, Nn);
    k_gemm2<<<mt, 128, G2_SMEM>>>(x, b2, gamma, beta, (float*)d_out, Nn);
}

// round 12
// speedup vs baseline: 1.0276x; 1.0276x over previous
#include <cuda_runtime.h>
#include <cuda_fp16.h>
#include <cstdint>

// ---------------------------------------------------------------------------
// ResidualGNNLayer (sm_103, fp16 mma.sync, 64x64 warp tiles, 3 CTAs/SM):
//   k_prep: detect + zero + W1/W2 fp16 transpose + x->fp16
//   k_edge: bucket edges; k_feat: 2 nodes/warp fp16 gather-mean
//   k_gemm1: h = relu(feat@W1 + b1 + rank2(deg,md))
//   k_gemm2: out = LN(x + h@W2 + b2)
//   GEMMs: 128 thr / 4 warps (2x2) of 64x64, BK=32, 3-stage,
//          __launch_bounds__(128,3) -> 12 warps/SM (reg-capped at 170).
// ---------------------------------------------------------------------------

#define DD 128
#define HH 512
#define KP 256
#define CAP 128
#define NN_MAX 50048    // 391 * 128

static __device__ int   g_is64;
static __device__ int   g_cnt[NN_MAX];
static __device__ float g_dist[NN_MAX];
static __device__ int   g_slots[NN_MAX * CAP];

static __device__ __half g_xh[(size_t)NN_MAX * DD];
static __device__ __half g_feat[(size_t)NN_MAX * KP];
static __device__ __half g_h[(size_t)NN_MAX * HH];
static __device__ __half g_w1t[HH * KP];              // [n=512][k=256]
static __device__ __half g_w2t[DD * HH];              // [n=128][k=512]

// ---------------- PTX helpers ----------------------------------------------
__device__ __forceinline__ uint32_t smem_u32(const void* p) {
    uint32_t a;
    asm("{ .reg .u64 t; cvta.to.shared.u64 t, %1; cvt.u32.u64 %0, t; }"
        : "=r"(a) : "l"(p));
    return a;
}
__device__ __forceinline__ void cp16(uint32_t d, const void* s) {
    asm volatile("cp.async.ca.shared.global [%0], [%1], 16;" :: "r"(d), "l"(s));
}
#define CP_COMMIT() asm volatile("cp.async.commit_group;" ::: "memory")
#define CP_WAIT(n)  asm volatile("cp.async.wait_group %0;" :: "n"(n) : "memory")

__device__ __forceinline__ void ldm_x4(uint32_t addr, uint32_t r[4]) {
    asm volatile("ldmatrix.sync.aligned.m8n8.x4.shared.b16 {%0,%1,%2,%3}, [%4];"
                 : "=r"(r[0]), "=r"(r[1]), "=r"(r[2]), "=r"(r[3]) : "r"(addr));
}
__device__ __forceinline__ void mma16816(float d[4], const uint32_t a[4],
                                         const uint32_t b0, const uint32_t b1) {
    asm volatile(
        "mma.sync.aligned.m16n8k16.row.col.f32.f16.f16.f32 "
        "{%0,%1,%2,%3},{%4,%5,%6,%7},{%8,%9},{%0,%1,%2,%3};"
        : "+f"(d[0]), "+f"(d[1]), "+f"(d[2]), "+f"(d[3])
        : "r"(a[0]), "r"(a[1]), "r"(a[2]), "r"(a[3]), "r"(b0), "r"(b1));
}
__device__ __forceinline__ uint32_t swz(int r, int c) {
    return (uint32_t)(r * 64 + (((((c >> 4) ^ (r >> 1)) & 3) << 4) | (c & 15)));
}

// ---------------- prep ------------------------------------------------------
__global__ void k_prep(const float* __restrict__ W1, const float* __restrict__ W2,
                       const float* __restrict__ x,
                       const void* __restrict__ eraw, int E, int Nn) {
    int b = blockIdx.x, t = threadIdx.x;
    if (b == 0) {
        if (t == 0) {
            const long long* p64 = (const long long*)eraw;
            int ok64 = 1;
            int step = E / 32; if (step < 1) step = 1;
            for (int i = 0; i < 32; i++) {
                long long idx = (long long)i * step;
                if (idx >= E) break;
                long long v = p64[idx];
                if (v < 0 || v >= Nn) { ok64 = 0; break; }
            }
            g_is64 = ok64;
        }
        return;
    }
    int ZB = (Nn + 255) / 256;
    if (b - 1 < ZB) {
        int i = (b - 1) * 256 + t;
        if (i < Nn) { g_cnt[i] = 0; g_dist[i] = 0.f; }
        return;
    }
    int b2 = b - 1 - ZB;
    if (b2 < (HH * KP) / 256) {
        int idx = b2 * 256 + t;
        int n = idx >> 8, k = idx & 255;
        g_w1t[idx] = __float2half_rn(W1[k * HH + n]);
        return;
    }
    int b3 = b2 - (HH * KP) / 256;
    if (b3 < (DD * HH) / 256) {
        int idx = b3 * 256 + t;
        int n = idx >> 9, k = idx & 511;
        g_w2t[idx] = __float2half_rn(W2[k * DD + n]);
        return;
    }
    int b4 = b3 - (DD * HH) / 256;
    int idx = b4 * 256 + t;
    if (idx < Nn * DD) g_xh[idx] = __float2half_rn(x[idx]);
}

__global__ void k_edge(const void* __restrict__ eraw,
                       const float* __restrict__ ed, int E, int Nn) {
    int e = blockIdx.x * blockDim.x + threadIdx.x;
    if (e >= E) return;
    int src, dst;
    if (g_is64) {
        const long long* p = (const long long*)eraw;
        src = (int)p[e]; dst = (int)p[E + e];
    } else {
        const int* p = (const int*)eraw;
        src = p[e]; dst = p[E + e];
    }
    src = min(max(src, 0), Nn - 1);
    dst = min(max(dst, 0), Nn - 1);
    int p = atomicAdd(&g_cnt[src], 1);
    if (p < CAP) g_slots[src * CAP + p] = dst;
    atomicAdd(&g_dist[src], ed[e]);
}

// 2 nodes per warp: 16 lanes x uint4 (16B) per row
__global__ void k_feat(const float* __restrict__ degrees, int Nn) {
    int warp = (blockIdx.x * blockDim.x + threadIdx.x) >> 5;
    int lane = threadIdx.x & 31;
    int sub = lane >> 4, sl = lane & 15;
    int gw = warp * 2 + sub;
    if (gw >= Nn) return;
    int cnt = g_cnt[gw]; if (cnt > CAP) cnt = CAP;
    const int* slots = g_slots + gw * CAP;
    float acc[8];
#pragma unroll
    for (int i = 0; i < 8; i++) acc[i] = 0.f;
    int dnext = (cnt > 0) ? slots[0] : 0;
    for (int j = 0; j < cnt; j++) {
        int dcur = dnext;
        if (j + 1 < cnt) dnext = slots[j + 1];
        uint4 u = *(const uint4*)(g_xh + (size_t)dcur * DD + sl * 8);
        float2 f0 = __half22float2(*(__half2*)&u.x);
        float2 f1 = __half22float2(*(__half2*)&u.y);
        float2 f2 = __half22float2(*(__half2*)&u.z);
        float2 f3 = __half22float2(*(__half2*)&u.w);
        acc[0] += f0.x; acc[1] += f0.y; acc[2] += f1.x; acc[3] += f1.y;
        acc[4] += f2.x; acc[5] += f2.y; acc[6] += f3.x; acc[7] += f3.y;
    }
    float inv = 1.f / fmaxf(degrees[gw], 1.f);
    __half* f = g_feat + (size_t)gw * KP;
    *(uint4*)(f + sl * 8) = *(const uint4*)(g_xh + (size_t)gw * DD + sl * 8);
    uint4 o;
    *(__half2*)&o.x = __floats2half2_rn(acc[0] * inv, acc[1] * inv);
    *(__half2*)&o.y = __floats2half2_rn(acc[2] * inv, acc[3] * inv);
    *(__half2*)&o.z = __floats2half2_rn(acc[4] * inv, acc[5] * inv);
    *(__half2*)&o.w = __floats2half2_rn(acc[6] * inv, acc[7] * inv);
    *(uint4*)(f + DD + sl * 8) = o;
}

// ---------------------------------------------------------------------------
// GEMM common: CTA 128x128, 4 warps (2x2) of 64x64, BK=32, 3 stages of 16KB.
// ---------------------------------------------------------------------------
#define STG(s) ((s) * 16384)

struct Frag64 {
    uint32_t Ah[4][4];
    uint32_t Bh[8][2];
};
__device__ __forceinline__ void load_f(uint32_t sb, uint32_t aoff, uint32_t boff,
                                       Frag64& f) {
#pragma unroll
    for (int mf = 0; mf < 4; mf++)
        ldm_x4(sb + aoff + mf * 1024, f.Ah[mf]);
#pragma unroll
    for (int p = 0; p < 4; p++) {
        uint32_t r[4];
        ldm_x4(sb + boff + p * 1024, r);
        f.Bh[p * 2 + 0][0] = r[0]; f.Bh[p * 2 + 0][1] = r[2];
        f.Bh[p * 2 + 1][0] = r[1]; f.Bh[p * 2 + 1][1] = r[3];
    }
}
__device__ __forceinline__ void mma_all64(float acc[4][8][4], const Frag64& f) {
#pragma unroll
    for (int mf = 0; mf < 4; mf++)
#pragma unroll
        for (int nf = 0; nf < 8; nf++)
            mma16816(acc[mf][nf], f.Ah[mf], f.Bh[nf][0], f.Bh[nf][1]);
}

// ---------------------------------------------------------------------------
// GEMM1: h = relu(feat @ W1 + b1 + deg*W1[256] + md*W1[257]); K=256, 8 steps
// ---------------------------------------------------------------------------
#define G1_SMEM 50176
__global__ __launch_bounds__(128, 3) void k_gemm1(
    const float* __restrict__ W1, const float* __restrict__ b1,
    const float* __restrict__ degrees, int Nn) {
    extern __shared__ __align__(128) char sm[];
    uint32_t base = smem_u32(sm);
    int t = threadIdx.x, lane = t & 31, wid = t >> 5;
    int wm = wid >> 1, wn = wid & 1;
    int row0 = blockIdx.x * 128, col0 = blockIdx.y * 128;

    float* degv = (float*)(sm + 49152);
    float* mdv  = (float*)(sm + 49664);
    {
        int gr = row0 + t;
        float dr = (gr < Nn) ? degrees[gr] : 0.f;
        float ds = (gr < Nn) ? g_dist[gr] : 0.f;
        degv[t] = dr;
        mdv[t]  = ds / fmaxf(dr, 1.f);
    }

    float acc[4][8][4];
#pragma unroll
    for (int a = 0; a < 4; a++)
#pragma unroll
        for (int b = 0; b < 8; b++)
#pragma unroll
            for (int c = 0; c < 4; c++) acc[a][b][c] = 0.f;

    uint32_t aoff = swz(wm * 64 + (lane & 15), (lane >> 4) * 16);
    uint32_t boff = 8192 + swz(wn * 64 + (lane & 15), (lane >> 4) * 16);

    int lr = t >> 2, seg = (t & 3) * 16;
    const char* pA = (const char*)(g_feat + (size_t)(row0 + lr) * KP) + seg;
    const char* pB = (const char*)(g_w1t + (size_t)(col0 + lr) * KP) + seg;
    uint32_t dA = base + swz(lr, seg);
    const int RB = KP * 2 * 32;   // 32 source rows = 16384 B

#pragma unroll 1
    for (int s = 0; s < 2; s++) {
#pragma unroll
        for (int i = 0; i < 4; i++) {
            cp16(dA + STG(s) + 2048 * i, pA + i * RB + s * 64);
            cp16(dA + STG(s) + 8192 + 2048 * i, pB + i * RB + s * 64);
        }
        CP_COMMIT();
    }
#pragma unroll 1
    for (int s = 0; s < 8; s++) {
        if (s < 7) { CP_WAIT(1); } else { CP_WAIT(0); }
        __syncthreads();
        if (s + 2 < 8) {
            int sp = (s + 2) % 3;
#pragma unroll
            for (int i = 0; i < 4; i++) {
                cp16(dA + STG(sp) + 2048 * i, pA + i * RB + (s + 2) * 64);
                cp16(dA + STG(sp) + 8192 + 2048 * i, pB + i * RB + (s + 2) * 64);
            }
            CP_COMMIT();
        }
        uint32_t sb = base + STG(s % 3);
#pragma unroll
        for (int ks = 0; ks < 2; ks++) {
            Frag64 f;
            load_f(sb, aoff ^ (ks * 32u), boff ^ (ks * 32u), f);
            mma_all64(acc, f);
        }
    }

    // epilogue: bias + rank2 + relu -> g_h fp16
#pragma unroll
    for (int nf = 0; nf < 8; nf++) {
        int cg = col0 + wn * 64 + nf * 8 + (lane & 3) * 2;
        float b10 = __ldg(b1 + cg), b11 = __ldg(b1 + cg + 1);
        float wd0 = __ldg(W1 + 256 * HH + cg), wd1 = __ldg(W1 + 256 * HH + cg + 1);
        float wq0 = __ldg(W1 + 257 * HH + cg), wq1 = __ldg(W1 + 257 * HH + cg + 1);
#pragma unroll
        for (int mf = 0; mf < 4; mf++) {
            int rl = wm * 64 + mf * 16 + (lane >> 2);
            float d0 = degv[rl], m0 = mdv[rl];
            float d1 = degv[rl + 8], m1 = mdv[rl + 8];
            float v00 = fmaxf(acc[mf][nf][0] + b10 + d0 * wd0 + m0 * wq0, 0.f);
            float v01 = fmaxf(acc[mf][nf][1] + b11 + d0 * wd1 + m0 * wq1, 0.f);
            float v10 = fmaxf(acc[mf][nf][2] + b10 + d1 * wd0 + m1 * wq0, 0.f);
            float v11 = fmaxf(acc[mf][nf][3] + b11 + d1 * wd1 + m1 * wq1, 0.f);
            *(__half2*)(g_h + (size_t)(row0 + rl) * HH + cg) =
                __floats2half2_rn(v00, v01);
            *(__half2*)(g_h + (size_t)(row0 + rl + 8) * HH + cg) =
                __floats2half2_rn(v10, v11);
        }
    }
}

// ---------------------------------------------------------------------------
// GEMM2 + residual + LN: out = LN(x + h@W2 + b2); K=512, 16 steps
// ---------------------------------------------------------------------------
#define G2_SMEM 52224
__global__ __launch_bounds__(128, 3) void k_gemm2(
    const float* __restrict__ x, const float* __restrict__ b2,
    const float* __restrict__ gamma, const float* __restrict__ beta,
    float* __restrict__ out, int Nn) {
    extern __shared__ __align__(128) char sm[];
    uint32_t base = smem_u32(sm);
    int t = threadIdx.x, lane = t & 31, wid = t >> 5;
    int wm = wid >> 1, wn = wid & 1;
    int row0 = blockIdx.x * 128;
    float* part0 = (float*)(sm + 49152);
    float* part1 = (float*)(sm + 50176);
    float* mus   = (float*)(sm + 51200);
    float* rss   = (float*)(sm + 51712);

    float acc[4][8][4];
#pragma unroll
    for (int a = 0; a < 4; a++)
#pragma unroll
        for (int b = 0; b < 8; b++)
#pragma unroll
            for (int c = 0; c < 4; c++) acc[a][b][c] = 0.f;

    uint32_t aoff = swz(wm * 64 + (lane & 15), (lane >> 4) * 16);
    uint32_t boff = 8192 + swz(wn * 64 + (lane & 15), (lane >> 4) * 16);

    int lr = t >> 2, seg = (t & 3) * 16;
    const char* pA = (const char*)(g_h + (size_t)(row0 + lr) * HH) + seg;
    const char* pB = (const char*)(g_w2t + (size_t)lr * HH) + seg;
    uint32_t dA = base + swz(lr, seg);
    const int RB = HH * 2 * 32;   // 32 source rows = 32768 B

#pragma unroll 1
    for (int s = 0; s < 2; s++) {
#pragma unroll
        for (int i = 0; i < 4; i++) {
            cp16(dA + STG(s) + 2048 * i, pA + i * RB + s * 64);
            cp16(dA + STG(s) + 8192 + 2048 * i, pB + i * RB + s * 64);
        }
        CP_COMMIT();
    }
#pragma unroll 1
    for (int s = 0; s < 16; s++) {
        if (s < 15) { CP_WAIT(1); } else { CP_WAIT(0); }
        __syncthreads();
        if (s + 2 < 16) {
            int sp = (s + 2) % 3;
#pragma unroll
            for (int i = 0; i < 4; i++) {
                cp16(dA + STG(sp) + 2048 * i, pA + i * RB + (s + 2) * 64);
                cp16(dA + STG(sp) + 8192 + 2048 * i, pB + i * RB + (s + 2) * 64);
            }
            CP_COMMIT();
        }
        uint32_t sb = base + STG(s % 3);
#pragma unroll
        for (int ks = 0; ks < 2; ks++) {
            Frag64 f;
            load_f(sb, aoff ^ (ks * 32u), boff ^ (ks * 32u), f);
            mma_all64(acc, f);
        }
    }

    // epilogue: y = acc + b2 + x in regs; row stats via quad-shfl + smem
#pragma unroll
    for (int nf = 0; nf < 8; nf++) {
        int cc = wn * 64 + nf * 8 + (lane & 3) * 2;
        float b20 = __ldg(b2 + cc), b21 = __ldg(b2 + cc + 1);
#pragma unroll
        for (int mf = 0; mf < 4; mf++) {
            int g0 = row0 + wm * 64 + mf * 16 + (lane >> 2);
            float2 xv0 = make_float2(0.f, 0.f), xv1 = xv0;
            if (g0 < Nn)     xv0 = *(const float2*)(x + (size_t)g0 * DD + cc);
            if (g0 + 8 < Nn) xv1 = *(const float2*)(x + (size_t)(g0 + 8) * DD + cc);
            acc[mf][nf][0] += b20 + xv0.x;
            acc[mf][nf][1] += b21 + xv0.y;
            acc[mf][nf][2] += b20 + xv1.x;
            acc[mf][nf][3] += b21 + xv1.y;
        }
    }
#pragma unroll
    for (int mf = 0; mf < 4; mf++) {
#pragma unroll
        for (int h = 0; h < 2; h++) {
            float s0 = 0.f, s1 = 0.f;
#pragma unroll
            for (int nf = 0; nf < 8; nf++) {
                float a0 = acc[mf][nf][2 * h], a1 = acc[mf][nf][2 * h + 1];
                s0 += a0 + a1;
                s1 += a0 * a0 + a1 * a1;
            }
            s0 += __shfl_xor_sync(0xffffffffu, s0, 1);
            s1 += __shfl_xor_sync(0xffffffffu, s1, 1);
            s0 += __shfl_xor_sync(0xffffffffu, s0, 2);
            s1 += __shfl_xor_sync(0xffffffffu, s1, 2);
            if ((lane & 3) == 0) {
                int rl = wm * 64 + mf * 16 + (lane >> 2) + h * 8;
                part0[wn * 128 + rl] = s0;
                part1[wn * 128 + rl] = s1;
            }
        }
    }
    __syncthreads();
    {
        float s0 = part0[t] + part0[128 + t];
        float s1 = part1[t] + part1[128 + t];
        float mu = s0 * (1.f / 128.f);
        float var = s1 * (1.f / 128.f) - mu * mu;
        mus[t] = mu;
        rss[t] = rsqrtf(var + 1e-5f);
    }
    __syncthreads();
#pragma unroll
    for (int nf = 0; nf < 8; nf++) {
        int cc = wn * 64 + nf * 8 + (lane & 3) * 2;
        float gg0 = __ldg(gamma + cc), gg1 = __ldg(gamma + cc + 1);
        float be0 = __ldg(beta + cc), be1 = __ldg(beta + cc + 1);
#pragma unroll
        for (int mf = 0; mf < 4; mf++) {
            int rl = wm * 64 + mf * 16 + (lane >> 2);
            int g0 = row0 + rl;
            if (g0 < Nn) {
                float mu = mus[rl], rs = rss[rl];
                float2 o;
                o.x = (acc[mf][nf][0] - mu) * rs * gg0 + be0;
                o.y = (acc[mf][nf][1] - mu) * rs * gg1 + be1;
                *(float2*)(out + (size_t)g0 * DD + cc) = o;
            }
            if (g0 + 8 < Nn) {
                float mu = mus[rl + 8], rs = rss[rl + 8];
                float2 o;
                o.x = (acc[mf][nf][2] - mu) * rs * gg0 + be0;
                o.y = (acc[mf][nf][3] - mu) * rs * gg1 + be1;
                *(float2*)(out + (size_t)(g0 + 8) * DD + cc) = o;
            }
        }
    }
}

// ---------------------------------------------------------------------------
extern "C" void kernel_launch(void* const* d_in, const int* in_sizes, int n_in,
                              void* d_out, int out_size) {
    const float* x       = (const float*)d_in[0];
    const float* W1      = (const float*)d_in[1];
    const float* b1      = (const float*)d_in[2];
    const float* W2      = (const float*)d_in[3];
    const float* b2      = (const float*)d_in[4];
    const float* gamma   = (const float*)d_in[5];
    const float* beta    = (const float*)d_in[6];
    const void*  ei      = d_in[7];
    const float* ed      = (const float*)d_in[8];
    const float* degrees = (const float*)d_in[9];

    int Nn = in_sizes[0] / DD;
    int E  = in_sizes[8];

    cudaFuncSetAttribute(k_gemm1, cudaFuncAttributeMaxDynamicSharedMemorySize, G1_SMEM);
    cudaFuncSetAttribute(k_gemm2, cudaFuncAttributeMaxDynamicSharedMemorySize, G2_SMEM);

    int ZB = (Nn + 255) / 256;
    int XB = (Nn * DD + 255) / 256;
    int prep_blocks = 1 + ZB + (HH * KP) / 256 + (DD * HH) / 256 + XB;
    k_prep<<<prep_blocks, 256>>>(W1, W2, x, ei, E, Nn);
    k_edge<<<(E + 255) / 256, 256>>>(ei, ed, E, Nn);
    k_feat<<<(Nn + 15) / 16, 256>>>(degrees, Nn);

    int mt = (Nn + 127) / 128;  // 391
    k_gemm1<<<dim3(mt, 4), 128, G1_SMEM>>>(W1, b1, degrees, Nn);
    k_gemm2<<<mt, 128, G2_SMEM>>>(x, b2, gamma, beta, (float*)d_out, Nn);
}